// round 1
// baseline (speedup 1.0000x reference)
#include <cuda_runtime.h>
#include <math.h>

// Problem constants
// B=4, C=256, H=W=32, NH=8, HC=32, G=4, GC=64, ns=1024, KK=5, ORF=2
// rpe table per head: 63x63

// ---------------- scratch (static device memory; no allocations) ------------
__device__ float g_q [4 * 256 * 1024];   // q conv output          (b, ch, p)
__device__ float g_xs[4 * 256 * 1024];   // sampled x              (b, ch, n)
__device__ float g_k [4 * 256 * 1024];
__device__ float g_v [4 * 256 * 1024];
__device__ float g_o [4 * 256 * 1024];   // attention output       (b, ch, m)
__device__ float g_pos[16 * 1024 * 2];   // pos per (bg, n, comp)

// ---------------- generic 1x1-conv SGEMM: Y[b,m,n] = sum_k W[m,k] X[b,k,n] + bias[m]
// M=256, N=1024, K=256, batch = gridDim.z
__global__ __launch_bounds__(256)
void gemm_conv(const float* __restrict__ Wm, const float* __restrict__ X,
               const float* __restrict__ bias, float* __restrict__ Y)
{
    const int b  = blockIdx.z;
    const int m0 = blockIdx.y * 64;
    const int n0 = blockIdx.x * 64;

    __shared__ float As[16][64];   // [k][m]
    __shared__ float Bs[16][64];   // [k][n]

    const int tid = threadIdx.x;
    const int tx = tid & 15;       // n micro
    const int ty = tid >> 4;       // m micro

    float acc[4][4];
#pragma unroll
    for (int i = 0; i < 4; i++)
#pragma unroll
        for (int j = 0; j < 4; j++) acc[i][j] = 0.f;

    const float* Xb = X + b * 262144;

    const int am = tid >> 2;             // 0..63
    const int ak = (tid & 3) * 4;        // 0,4,8,12
    const int bn = tid & 63;
    const int bk = (tid >> 6) * 4;

    for (int k0 = 0; k0 < 256; k0 += 16) {
        float4 w4 = *(const float4*)&Wm[(m0 + am) * 256 + k0 + ak];
        As[ak + 0][am] = w4.x;
        As[ak + 1][am] = w4.y;
        As[ak + 2][am] = w4.z;
        As[ak + 3][am] = w4.w;
#pragma unroll
        for (int u = 0; u < 4; u++)
            Bs[bk + u][bn] = Xb[(k0 + bk + u) * 1024 + n0 + bn];
        __syncthreads();

#pragma unroll
        for (int kk = 0; kk < 16; kk++) {
            float4 a4 = *(const float4*)&As[kk][ty * 4];
            float4 b4 = *(const float4*)&Bs[kk][tx * 4];
            float a[4] = {a4.x, a4.y, a4.z, a4.w};
            float bb[4] = {b4.x, b4.y, b4.z, b4.w};
#pragma unroll
            for (int i = 0; i < 4; i++)
#pragma unroll
                for (int j = 0; j < 4; j++)
                    acc[i][j] = fmaf(a[i], bb[j], acc[i][j]);
        }
        __syncthreads();
    }

#pragma unroll
    for (int i = 0; i < 4; i++) {
        float bv = bias[m0 + ty * 4 + i];
        float4 o4 = make_float4(acc[i][0] + bv, acc[i][1] + bv,
                                acc[i][2] + bv, acc[i][3] + bv);
        *(float4*)&Y[b * 262144 + (m0 + ty * 4 + i) * 1024 + n0 + tx * 4] = o4;
    }
}

// ---------------- offset pipeline: dwconv5x5 + LN + GELU + proj + tanh -> pos
__global__ __launch_bounds__(256)
void offset_kernel(const float* __restrict__ q, const float* __restrict__ w_dw,
                   const float* __restrict__ b_dw, const float* __restrict__ ln_g,
                   const float* __restrict__ ln_b, const float* __restrict__ wpj,
                   float* __restrict__ pos_buf, float* __restrict__ out_pos,
                   float* __restrict__ out_ref)
{
    __shared__ float sw[1600];
    __shared__ float sb[64], sg[64], sbt[64], spj0[64], spj1[64];
    const int tid = threadIdx.x;
    for (int t = tid; t < 1600; t += 256) sw[t] = w_dw[t];
    if (tid < 64) {
        sb[tid] = b_dw[tid]; sg[tid] = ln_g[tid]; sbt[tid] = ln_b[tid];
        spj0[tid] = wpj[tid]; spj1[tid] = wpj[64 + tid];
    }
    __syncthreads();

    const int pix = blockIdx.x * 256 + tid;     // bg*1024 + i*32 + j
    const int bg  = pix >> 10;
    const int p   = pix & 1023;
    const int i   = p >> 5, j = p & 31;
    const float* qb = q + bg * 65536;

    // pass A: mean / var over 64 channels of conv output
    float s1 = 0.f, s2 = 0.f;
    for (int c = 0; c < 64; c++) {
        const float* qc = qb + c * 1024;
        const float* wc = sw + c * 25;
        float a = sb[c];
#pragma unroll
        for (int dy = 0; dy < 5; dy++) {
            int yy = i + dy - 2;
            if ((unsigned)yy > 31u) continue;
            const float* qr = qc + yy * 32;
#pragma unroll
            for (int dx = 0; dx < 5; dx++) {
                int xx = j + dx - 2;
                if ((unsigned)xx > 31u) continue;
                a = fmaf(qr[xx], wc[dy * 5 + dx], a);
            }
        }
        s1 += a;
        s2 = fmaf(a, a, s2);
    }
    float mu   = s1 * 0.015625f;
    float var  = s2 * 0.015625f - mu * mu;
    float rstd = rsqrtf(var + 1e-5f);

    // pass B: recompute conv, LN+GELU, project to 2
    float o0 = 0.f, o1 = 0.f;
    for (int c = 0; c < 64; c++) {
        const float* qc = qb + c * 1024;
        const float* wc = sw + c * 25;
        float a = sb[c];
#pragma unroll
        for (int dy = 0; dy < 5; dy++) {
            int yy = i + dy - 2;
            if ((unsigned)yy > 31u) continue;
            const float* qr = qc + yy * 32;
#pragma unroll
            for (int dx = 0; dx < 5; dx++) {
                int xx = j + dx - 2;
                if ((unsigned)xx > 31u) continue;
                a = fmaf(qr[xx], wc[dy * 5 + dx], a);
            }
        }
        float t  = fmaf((a - mu) * rstd, sg[c], sbt[c]);
        float gl = 0.5f * t * (1.f + erff(t * 0.70710678118654752f));
        o0 = fmaf(gl, spj0[c], o0);
        o1 = fmaf(gl, spj1[c], o1);
    }
    float off0 = tanhf(o0) * 0.0625f;   // (1/Hk)*ORF = 1/16
    float off1 = tanhf(o1) * 0.0625f;
    float r0 = (j + 0.5f) * 0.0625f - 1.f;
    float r1 = (i + 0.5f) * 0.0625f - 1.f;
    float P0 = off0 + r0, P1 = off1 + r1;

    pos_buf[pix * 2]     = P0;
    pos_buf[pix * 2 + 1] = P1;
    out_pos[pix * 2]     = P0;
    out_pos[pix * 2 + 1] = P1;
    out_ref[pix * 2]     = r0;
    out_ref[pix * 2 + 1] = r1;
}

// ---------------- bilinear sample of x at pos -> xs (b, ch, n)
__global__ __launch_bounds__(256)
void sample_kernel(const float* __restrict__ x, const float* __restrict__ pos_buf,
                   float* __restrict__ xs)
{
    const int idx = blockIdx.x * 256 + threadIdx.x;   // bg*1024 + n
    const float P0 = pos_buf[idx * 2];
    const float P1 = pos_buf[idx * 2 + 1];
    // grid reversed: gx = P1, gy = P0 ; align_corners scaling (Wi-1)/2 = 15.5
    const float gxp = (P1 + 1.f) * 15.5f;
    const float gyp = (P0 + 1.f) * 15.5f;
    float x0f = floorf(gxp), y0f = floorf(gyp);
    float x1f = x0f + 1.f,  y1f = y0f + 1.f;
    float wx1 = gxp - x0f, wx0 = 1.f - wx1;
    float wy1 = gyp - y0f, wy0 = 1.f - wy1;
    bool vx0 = (x0f >= 0.f) && (x0f <= 31.f);
    bool vx1 = (x1f >= 0.f) && (x1f <= 31.f);
    bool vy0 = (y0f >= 0.f) && (y0f <= 31.f);
    bool vy1 = (y1f >= 0.f) && (y1f <= 31.f);
    int X0 = (int)fminf(fmaxf(x0f, 0.f), 31.f);
    int X1 = (int)fminf(fmaxf(x1f, 0.f), 31.f);
    int Y0 = (int)fminf(fmaxf(y0f, 0.f), 31.f);
    int Y1 = (int)fminf(fmaxf(y1f, 0.f), 31.f);
    float w00 = (vy0 && vx0) ? wy0 * wx0 : 0.f;
    float w01 = (vy0 && vx1) ? wy0 * wx1 : 0.f;
    float w10 = (vy1 && vx0) ? wy1 * wx0 : 0.f;
    float w11 = (vy1 && vx1) ? wy1 * wx1 : 0.f;
    int i00 = Y0 * 32 + X0, i01 = Y0 * 32 + X1;
    int i10 = Y1 * 32 + X0, i11 = Y1 * 32 + X1;

    const int bg = idx >> 10, n = idx & 1023;
    const float* xb = x + bg * 65536;
    float* xo = xs + bg * 65536 + n;
    for (int c = 0; c < 64; c++) {
        const float* xc = xb + c * 1024;
        float vout = w00 * xc[i00] + w01 * xc[i01] + w10 * xc[i10] + w11 * xc[i11];
        xo[c * 1024] = vout;
    }
}

// ---------------- RPE bilinear (63x63 table, zeros padding, align_corners)
__device__ __forceinline__ float bias_sample(const float* __restrict__ rpe,
                                             float qg0, float qg1,
                                             float p0, float p1)
{
    float gy  = (qg0 - p0) * 0.5f;
    float gx  = (qg1 - p1) * 0.5f;
    float gxp = (gx + 1.f) * 31.f;   // 0.5*(63-1)
    float gyp = (gy + 1.f) * 31.f;
    float x0f = floorf(gxp), y0f = floorf(gyp);
    float x1f = x0f + 1.f,  y1f = y0f + 1.f;
    float wx1 = gxp - x0f, wx0 = 1.f - wx1;
    float wy1 = gyp - y0f, wy0 = 1.f - wy1;
    bool vx0 = (x0f >= 0.f) && (x0f <= 62.f);
    bool vx1 = (x1f >= 0.f) && (x1f <= 62.f);
    bool vy0 = (y0f >= 0.f) && (y0f <= 62.f);
    bool vy1 = (y1f >= 0.f) && (y1f <= 62.f);
    int X0 = (int)fminf(fmaxf(x0f, 0.f), 62.f);
    int X1 = (int)fminf(fmaxf(x1f, 0.f), 62.f);
    int Y0 = (int)fminf(fmaxf(y0f, 0.f), 62.f);
    int Y1 = (int)fminf(fmaxf(y1f, 0.f), 62.f);
    float v00 = (vy0 && vx0) ? __ldg(&rpe[Y0 * 63 + X0]) : 0.f;
    float v01 = (vy0 && vx1) ? __ldg(&rpe[Y0 * 63 + X1]) : 0.f;
    float v10 = (vy1 && vx0) ? __ldg(&rpe[Y1 * 63 + X0]) : 0.f;
    float v11 = (vy1 && vx1) ? __ldg(&rpe[Y1 * 63 + X1]) : 0.f;
    return v00 * (wy0 * wx0) + v01 * (wy0 * wx1) +
           v10 * (wy1 * wx0) + v11 * (wy1 * wx1);
}

// ---------------- fused attention: QK^T*scale + rpe-bias, online softmax, PV
// grid: (16 m-tiles, 32 heads), 256 threads (8 warps); warp w: rows w*8..w*8+7
// lane handles n = 2*lane, 2*lane+1 within a 64-wide n tile; PV channel = lane.
__global__ __launch_bounds__(256, 2)
void attn_kernel(const float* __restrict__ q, const float* __restrict__ k,
                 const float* __restrict__ v, const float* __restrict__ rpe,
                 const float* __restrict__ pos, float* __restrict__ out)
{
    const int bh = blockIdx.y;
    const int b  = bh >> 3, h = bh & 7;
    const int g  = h >> 1;
    const int bg = b * 4 + g;
    const int m0 = blockIdx.x * 64;
    const float* rpe_h = rpe + h * 3969;

    __shared__ float sQ[32 * 64];     // [c][m], broadcast reads
    __shared__ float sK[32 * 66];     // [c][n], pad 66 for float2 lane reads
    __shared__ float sV[32 * 68];     // [c][n], pad 68 for conflict-free float4
    __shared__ float sP[8 * 8 * 64];  // per-warp prob tiles
    __shared__ float sPos[128];       // 64 n x 2

    const int tid  = threadIdx.x;
    const int w    = tid >> 5;
    const int lane = tid & 31;

    const float* qh = q + (b * 256 + h * 32) * 1024;
    const float* kh = k + (b * 256 + h * 32) * 1024;
    const float* vh = v + (b * 256 + h * 32) * 1024;

    for (int idx = tid; idx < 2048; idx += 256) {
        int c = idx >> 6, mm = idx & 63;
        sQ[c * 64 + mm] = qh[c * 1024 + m0 + mm];
    }

    float M[8], L[8], acc[8], qg0[8], qg1[8];
#pragma unroll
    for (int r = 0; r < 8; r++) {
        M[r] = -1e30f; L[r] = 0.f; acc[r] = 0.f;
        int mg = m0 + w * 8 + r;
        qg0[r] = ((mg & 31) + 0.5f) * 0.0625f - 1.f;
        qg1[r] = ((mg >> 5) + 0.5f) * 0.0625f - 1.f;
    }

    const float scale = 0.17677669529663687f;   // 32^-0.5

    for (int nt = 0; nt < 16; nt++) {
        const int n0 = nt * 64;
        __syncthreads();
        for (int idx = tid; idx < 2048; idx += 256) {
            int c = idx >> 6, nn = idx & 63;
            sK[c * 66 + nn] = kh[c * 1024 + n0 + nn];
            sV[c * 68 + nn] = vh[c * 1024 + n0 + nn];
        }
        if (tid < 128) sPos[tid] = pos[bg * 2048 + n0 * 2 + tid];
        __syncthreads();

        // ---- scores: 8 rows x 2 n per lane
        float s0[8], s1[8];
#pragma unroll
        for (int r = 0; r < 8; r++) { s0[r] = 0.f; s1[r] = 0.f; }
#pragma unroll
        for (int c = 0; c < 32; c++) {
            float2 kv = *(const float2*)&sK[c * 66 + (lane << 1)];
            const float* qrow = &sQ[c * 64 + (w << 3)];
            float4 qa = *(const float4*)qrow;
            float4 qb = *(const float4*)(qrow + 4);
            float qv[8] = {qa.x, qa.y, qa.z, qa.w, qb.x, qb.y, qb.z, qb.w};
#pragma unroll
            for (int r = 0; r < 8; r++) {
                s0[r] = fmaf(qv[r], kv.x, s0[r]);
                s1[r] = fmaf(qv[r], kv.y, s1[r]);
            }
        }

        // ---- bias + online softmax
        float4 pA = *(const float4*)&sPos[lane << 2];  // pos[n0+2l], pos[n0+2l+1]
#pragma unroll
        for (int r = 0; r < 8; r++) {
            float sc0 = fmaf(s0[r], scale, bias_sample(rpe_h, qg0[r], qg1[r], pA.x, pA.y));
            float sc1 = fmaf(s1[r], scale, bias_sample(rpe_h, qg0[r], qg1[r], pA.z, pA.w));
            float tm = fmaxf(sc0, sc1);
#pragma unroll
            for (int o = 16; o; o >>= 1) tm = fmaxf(tm, __shfl_xor_sync(0xffffffffu, tm, o));
            float newM = fmaxf(M[r], tm);
            float p0v = __expf(sc0 - newM);
            float p1v = __expf(sc1 - newM);
            float alpha = __expf(M[r] - newM);
            float ps = p0v + p1v;
#pragma unroll
            for (int o = 16; o; o >>= 1) ps += __shfl_xor_sync(0xffffffffu, ps, o);
            L[r] = L[r] * alpha + ps;
            acc[r] *= alpha;
            M[r] = newM;
            *(float2*)&sP[((w << 3) + r) * 64 + (lane << 1)] = make_float2(p0v, p1v);
        }
        __syncwarp();

        // ---- PV: channel = lane, acc over this n tile
#pragma unroll
        for (int nb = 0; nb < 64; nb += 4) {
            float4 vv = *(const float4*)&sV[lane * 68 + nb];
#pragma unroll
            for (int r = 0; r < 8; r++) {
                float4 pp = *(const float4*)&sP[((w << 3) + r) * 64 + nb];
                acc[r] = fmaf(pp.x, vv.x, acc[r]);
                acc[r] = fmaf(pp.y, vv.y, acc[r]);
                acc[r] = fmaf(pp.z, vv.z, acc[r]);
                acc[r] = fmaf(pp.w, vv.w, acc[r]);
            }
        }
    }

#pragma unroll
    for (int r = 0; r < 8; r++)
        out[(b * 256 + h * 32 + lane) * 1024 + m0 + (w << 3) + r] = acc[r] / L[r];
}

// ---------------- launch ----------------
extern "C" void kernel_launch(void* const* d_in, const int* in_sizes, int n_in,
                              void* d_out, int out_size)
{
    const float* x        = (const float*)d_in[0];
    const float* wq       = (const float*)d_in[1];
    const float* bq       = (const float*)d_in[2];
    const float* w_off_dw = (const float*)d_in[3];
    const float* b_off_dw = (const float*)d_in[4];
    const float* ln_g     = (const float*)d_in[5];
    const float* ln_b     = (const float*)d_in[6];
    const float* w_off_pj = (const float*)d_in[7];
    const float* wk       = (const float*)d_in[8];
    const float* bk       = (const float*)d_in[9];
    const float* wv       = (const float*)d_in[10];
    const float* bv       = (const float*)d_in[11];
    const float* wo       = (const float*)d_in[12];
    const float* bo       = (const float*)d_in[13];
    const float* rpe      = (const float*)d_in[14];
    float* out = (float*)d_out;

    float *qb, *xsb, *kb, *vb, *ob, *posb;
    cudaGetSymbolAddress((void**)&qb,   g_q);
    cudaGetSymbolAddress((void**)&xsb,  g_xs);
    cudaGetSymbolAddress((void**)&kb,   g_k);
    cudaGetSymbolAddress((void**)&vb,   g_v);
    cudaGetSymbolAddress((void**)&ob,   g_o);
    cudaGetSymbolAddress((void**)&posb, g_pos);

    const dim3 gg(16, 4, 4);

    // 1. q = wq * x + bq
    gemm_conv<<<gg, 256>>>(wq, x, bq, qb);
    // 2. offsets -> pos (also writes pos/ref output sections)
    offset_kernel<<<64, 256>>>(qb, w_off_dw, b_off_dw, ln_g, ln_b, w_off_pj,
                               posb, out + 1048576, out + 1048576 + 32768);
    // 3. bilinear sample x at pos -> xs
    sample_kernel<<<64, 256>>>(x, posb, xsb);
    // 4. k, v projections
    gemm_conv<<<gg, 256>>>(wk, xsb, bk, kb);
    gemm_conv<<<gg, 256>>>(wv, xsb, bv, vb);
    // 5. fused attention (QK^T*scale + rpe bias, softmax, PV)
    attn_kernel<<<dim3(16, 32), 256>>>(qb, kb, vb, rpe, posb, ob);
    // 6. y = wo * out + bo  -> d_out[0 : 1048576]
    gemm_conv<<<gg, 256>>>(wo, ob, bo, out);
}